// round 9
// baseline (speedup 1.0000x reference)
#include <cuda_runtime.h>
#include <math.h>

// Persistent fused CNN + analytic quantum circuit.
// grid = 3*148 CTAs x 320 threads; dynamic image-pair scheduling via a global
// counter (reset by a tiny kernel each launch). Weights loaded to smem ONCE per
// CTA. conv2 fuses relu + 2x2 maxpool in registers. The quantum epilogue of
// pair k overlaps the image-load phase of pair k+1.
//
// Quantum part collapses analytically:
//   P_i(1) = (1 + sin f_i)/2
//   <Z_j>  = - sum_{b in {0,1}^4} prod_i P_i(b_i) * sin( sum_{i: b_i=1} w[i][j] )
//   out_j  = sigmoid(10 * <Z_j>)

__device__ int g_pair_counter;

__global__ void reset_kernel() { g_pair_counter = 0; }

// shared-memory layout (floats)
#define OFF_IMG   0        // [1600] phase A: pair's images [2*784]; phase B: s_p2 [2][800]
#define OFF_P1    1600     // [2][16][12][12] pooled conv1 (row = 12 floats, 16B-aligned)
#define OFF_W2    6208     // [4608] conv2 weights, native HWIO [k][ci][co]
#define OFF_W1    10816    // [144]
#define OFF_B1    10960    // [16]
#define OFF_B2    10976    // [32]
#define OFF_FEAT  11008    // [16] double-buffered (parity x 8)
#define OFF_PAIR  11024    // [2]  (ints) double-buffered next-pair index
#define SM_FLOATS 11028
#define SM_BYTES  (SM_FLOATS * 4)

__device__ __forceinline__ void do_quantum(int pair, const float* s_feat8,
                                           const float* __restrict__ qwg,
                                           float* __restrict__ out, int B, int tid)
{
    const int im = tid >> 2;
    const int j  = tid & 3;
    const int img = pair * 2 + im;
    if (img >= B) return;
    float pr1[4];
    #pragma unroll
    for (int i = 0; i < 4; i++) {
        const float f = tanhf(s_feat8[im * 4 + i]);
        pr1[i] = 0.5f * (1.0f + sinf(f));
    }
    float wj[4];
    #pragma unroll
    for (int i = 0; i < 4; i++) wj[i] = qwg[i * 4 + j];

    float q = 0.0f;
    #pragma unroll
    for (int b = 0; b < 16; b++) {
        float prob = 1.0f, ang = 0.0f;
        #pragma unroll
        for (int i = 0; i < 4; i++) {
            if (b & (1 << i)) { prob *= pr1[i];        ang += wj[i]; }
            else              { prob *= 1.0f - pr1[i]; }
        }
        q -= prob * sinf(ang);
    }
    out[img * 4 + j] = 1.0f / (1.0f + expf(-10.0f * q));
}

__global__ __launch_bounds__(320, 3)
void hybrid_kernel(const float* __restrict__ x,
                   const float* __restrict__ w1g, const float* __restrict__ b1g,
                   const float* __restrict__ w2g, const float* __restrict__ b2g,
                   const float* __restrict__ dwg, const float* __restrict__ dbg,
                   const float* __restrict__ qwg,
                   float* __restrict__ out, int B, int npairs)
{
    extern __shared__ __align__(16) float sm[];
    float* s_img  = sm + OFF_IMG;     // aliased with s_p2 (phases separated by bars)
    float* s_p2   = sm + OFF_IMG;
    float* s_p1   = sm + OFF_P1;
    float* s_w2   = sm + OFF_W2;
    float* s_w1   = sm + OFF_W1;
    float* s_b1   = sm + OFF_B1;
    float* s_b2   = sm + OFF_B2;
    float* s_feat = sm + OFF_FEAT;    // [2][8]
    int*   s_pair = (int*)(sm + OFF_PAIR);

    const int tid = threadIdx.x;

    // ---------------- one-time weight load ----------------
    {
        const float4* src = (const float4*)w2g;
        float4* dst = (float4*)s_w2;
        for (int i = tid; i < 1152; i += 320) dst[i] = src[i];
    }
    for (int i = tid; i < 144; i += 320) s_w1[i] = w1g[i];
    if (tid < 16) s_b1[tid] = b1g[tid];
    if (tid < 32) s_b2[tid] = b2g[tid];
    if (tid == 0) s_pair[0] = atomicAdd(&g_pair_counter, 1);
    __syncthreads();

    int it = 0;
    int prev = -1;

    while (true) {
        const int cur = s_pair[it & 1];
        if (cur >= npairs) break;
        const int par = it & 1;

        // ---- phase L: quantum(prev) on tid<8 overlaps image load(cur) ----
        if (tid < 8) {
            if (it > 0) do_quantum(prev, s_feat + ((it - 1) & 1) * 8, qwg, out, B, tid);
        } else {
            const int nimg = (cur * 2 + 1 < B) ? 2 : 1;
            const float* xin = x + cur * 2 * 784;
            const int cnt = nimg * 784;
            for (int i = tid - 8; i < cnt; i += 312) s_img[i] = xin[i];
        }
        if (tid >= 8 && tid < 16) s_feat[par * 8 + (tid - 8)] = dbg[(tid - 8) & 3];
        if (tid == 16) s_pair[(it + 1) & 1] = atomicAdd(&g_pair_counter, 1);
        __syncthreads();

        // ---- conv1 (3x3x1x16) + relu + 2x2 maxpool -> s_p1[2][16][12][12] ----
        for (int u = tid; u < 768; u += 320) {
            const int im   = u / 384;
            const int rem  = u - im * 384;
            const int half = rem & 1;
            const int idx  = rem >> 1;
            const int co   = idx & 15;
            const int py   = idx >> 4;
            float w[9];
            #pragma unroll
            for (int k = 0; k < 9; k++) w[k] = s_w1[k * 16 + co];
            const float bias = s_b1[co];
            const float* in0 = s_img + im * 784 + (2 * py) * 28;
            float* p1row = s_p1 + im * 2304 + (co * 12 + py) * 12;
            const int px0 = half * 6;

            float win[4][4];
            #pragma unroll
            for (int r = 0; r < 4; r++) {
                const float2 v = *(const float2*)(in0 + r * 28 + 2 * px0);
                win[r][2] = v.x; win[r][3] = v.y;
            }
            #pragma unroll
            for (int dpx = 0; dpx < 6; dpx++) {
                const int px = px0 + dpx;
                #pragma unroll
                for (int r = 0; r < 4; r++) {
                    win[r][0] = win[r][2];
                    win[r][1] = win[r][3];
                    const float2 v = *(const float2*)(in0 + r * 28 + 2 * px + 2);
                    win[r][2] = v.x; win[r][3] = v.y;
                }
                float best = -1e30f;
                #pragma unroll
                for (int dy = 0; dy < 2; dy++) {
                    #pragma unroll
                    for (int dx = 0; dx < 2; dx++) {
                        float acc = bias;
                        #pragma unroll
                        for (int ky = 0; ky < 3; ky++) {
                            #pragma unroll
                            for (int kx = 0; kx < 3; kx++)
                                acc += win[dy + ky][dx + kx] * w[ky * 3 + kx];
                        }
                        best = fmaxf(best, acc);
                    }
                }
                p1row[px] = fmaxf(best, 0.0f);
            }
        }
        __syncthreads();

        // ---- conv2 (3x3x16x32) + relu + FUSED 2x2 maxpool -> s_p2 ----
        {
            const int im  = tid >= 160;
            const int t   = tid - im * 160;    // mod-160 (not a pow2 mask!)
            const int co  = t & 31;
            const int oyp = t >> 5;            // 0..4
            const float bias = s_b2[co];
            float acc0[10], acc1[10];
            #pragma unroll
            for (int i = 0; i < 10; i++) { acc0[i] = bias; acc1[i] = bias; }

            const float* p1base = s_p1 + im * 2304;

            #pragma unroll 1
            for (int ci = 0; ci < 16; ci++) {
                const float* wbase = s_w2 + ci * 32 + co;
                float w[9];
                #pragma unroll
                for (int k = 0; k < 9; k++) w[k] = wbase[k * 512];

                const float* rb = p1base + (ci * 12 + 2 * oyp) * 12;
                #pragma unroll
                for (int r = 0; r < 4; r++) {
                    const float4* rp = (const float4*)(rb + r * 12);
                    const float4 A = rp[0], Bv = rp[1], C = rp[2];
                    const float a[12] = {A.x, A.y, A.z, A.w, Bv.x, Bv.y, Bv.z, Bv.w,
                                         C.x, C.y, C.z, C.w};
                    if (r < 3) {
                        const float w0 = w[r * 3], w1 = w[r * 3 + 1], w2 = w[r * 3 + 2];
                        #pragma unroll
                        for (int ox = 0; ox < 10; ox++) {
                            acc0[ox] += a[ox] * w0;
                            acc0[ox] += a[ox + 1] * w1;
                            acc0[ox] += a[ox + 2] * w2;
                        }
                    }
                    if (r >= 1) {
                        const float w0 = w[(r - 1) * 3], w1 = w[(r - 1) * 3 + 1],
                                    w2 = w[(r - 1) * 3 + 2];
                        #pragma unroll
                        for (int ox = 0; ox < 10; ox++) {
                            acc1[ox] += a[ox] * w0;
                            acc1[ox] += a[ox + 1] * w1;
                            acc1[ox] += a[ox + 2] * w2;
                        }
                    }
                }
            }
            float* dst = s_p2 + im * 800 + (oyp * 5) * 32 + co;
            #pragma unroll
            for (int c = 0; c < 5; c++) {
                const float m = fmaxf(fmaxf(acc0[2 * c], acc0[2 * c + 1]),
                                      fmaxf(acc1[2 * c], acc1[2 * c + 1]));
                dst[c * 32] = fmaxf(m, 0.0f);
            }
        }
        __syncthreads();

        // ---- dense 800 -> 4, both images ----
        {
            float pA0 = 0.f, pA1 = 0.f, pA2 = 0.f, pA3 = 0.f;
            float pB0 = 0.f, pB1 = 0.f, pB2 = 0.f, pB3 = 0.f;
            for (int k = tid; k < 800; k += 320) {
                const float vA = s_p2[k];
                const float vB = s_p2[800 + k];
                const float4 w = *(const float4*)(dwg + k * 4);
                pA0 += vA * w.x; pA1 += vA * w.y; pA2 += vA * w.z; pA3 += vA * w.w;
                pB0 += vB * w.x; pB1 += vB * w.y; pB2 += vB * w.z; pB3 += vB * w.w;
            }
            #pragma unroll
            for (int off = 16; off; off >>= 1) {
                pA0 += __shfl_down_sync(0xffffffffu, pA0, off);
                pA1 += __shfl_down_sync(0xffffffffu, pA1, off);
                pA2 += __shfl_down_sync(0xffffffffu, pA2, off);
                pA3 += __shfl_down_sync(0xffffffffu, pA3, off);
                pB0 += __shfl_down_sync(0xffffffffu, pB0, off);
                pB1 += __shfl_down_sync(0xffffffffu, pB1, off);
                pB2 += __shfl_down_sync(0xffffffffu, pB2, off);
                pB3 += __shfl_down_sync(0xffffffffu, pB3, off);
            }
            if ((tid & 31) == 0) {
                float* f = s_feat + par * 8;
                atomicAdd(&f[0], pA0);
                atomicAdd(&f[1], pA1);
                atomicAdd(&f[2], pA2);
                atomicAdd(&f[3], pA3);
                atomicAdd(&f[4], pB0);
                atomicAdd(&f[5], pB1);
                atomicAdd(&f[6], pB2);
                atomicAdd(&f[7], pB3);
            }
        }
        __syncthreads();

        prev = cur;
        it++;
    }

    // ---- epilogue: quantum for the last processed pair ----
    if (it > 0 && tid < 8)
        do_quantum(prev, s_feat + ((it - 1) & 1) * 8, qwg, out, B, tid);
}

extern "C" void kernel_launch(void* const* d_in, const int* in_sizes, int n_in,
                              void* d_out, int out_size)
{
    const float* x   = (const float*)d_in[0];
    const float* w1  = (const float*)d_in[1];
    const float* b1  = (const float*)d_in[2];
    const float* w2  = (const float*)d_in[3];
    const float* b2  = (const float*)d_in[4];
    const float* dw  = (const float*)d_in[5];
    const float* db  = (const float*)d_in[6];
    const float* qw  = (const float*)d_in[7];
    float* out = (float*)d_out;

    const int B = in_sizes[0] / 784;   // NHWC 28*28*1
    const int npairs = (B + 1) / 2;
    int grid = 3 * 148;
    if (grid > npairs) grid = npairs;

    reset_kernel<<<1, 1>>>();
    hybrid_kernel<<<grid, 320, SM_BYTES>>>(x, w1, b1, w2, b2, dw, db, qw,
                                           out, B, npairs);
}

// round 10
// speedup vs baseline: 1.0181x; 1.0181x over previous
#include <cuda_runtime.h>
#include <math.h>

// Fused CNN + analytic quantum circuit. One CTA per FOUR images, 320 threads,
// 2 CTAs/SM. conv2 thread = (pair-half, co, oy-pair) processes TWO images per
// weight load (40 accumulators) and fuses relu + 2x2 maxpool in registers.
//
// Quantum part collapses analytically:
//   P_i(1) = (1 + sin f_i)/2
//   <Z_j>  = - sum_{b in {0,1}^4} prod_i P_i(b_i) * sin( sum_{i: b_i=1} w[i][j] )
//   out_j  = sigmoid(10 * <Z_j>)

// dynamic shared-memory layout (floats)
#define OFF_IMG   0        // [3200] phase A: 4 images [4*784=3136]; phase B: s_p2 [4][800]
#define OFF_P1    3200     // [4][16][12][12] pooled conv1 (row = 12 floats, 16B-aligned)
#define OFF_W2    12416    // [4608] conv2 weights, native HWIO [k][ci][co]
#define OFF_W1    17024    // [144]
#define OFF_B1    17168    // [16]
#define OFF_B2    17184    // [32]
#define OFF_FEAT  17216    // [16] (dense out + bias, 4 images x 4)
#define SM_FLOATS 17232
#define SM_BYTES  (SM_FLOATS * 4)

__global__ __launch_bounds__(320, 2)
void hybrid_kernel(const float* __restrict__ x,
                   const float* __restrict__ w1g, const float* __restrict__ b1g,
                   const float* __restrict__ w2g, const float* __restrict__ b2g,
                   const float* __restrict__ dwg, const float* __restrict__ dbg,
                   const float* __restrict__ qwg,
                   float* __restrict__ out, int B)
{
    extern __shared__ __align__(16) float sm[];
    float* s_img  = sm + OFF_IMG;     // phase A
    float* s_p2   = sm + OFF_IMG;     // phase B (images dead after conv1)
    float* s_p1   = sm + OFF_P1;
    float* s_w2   = sm + OFF_W2;
    float* s_w1   = sm + OFF_W1;
    float* s_b1   = sm + OFF_B1;
    float* s_b2   = sm + OFF_B2;
    float* s_feat = sm + OFF_FEAT;

    const int tid  = threadIdx.x;
    const int img0 = blockIdx.x * 4;
    const int nimg = min(4, B - img0);

    // ---------------- load phase ----------------
    {
        const float* xin = x + img0 * 784;
        const int cnt = nimg * 784;
        for (int i = tid; i < cnt; i += 320) s_img[i] = xin[i];
    }
    {
        const float4* src = (const float4*)w2g;
        float4* dst = (float4*)s_w2;
        for (int i = tid; i < 1152; i += 320) dst[i] = src[i];
    }
    for (int i = tid; i < 144; i += 320) s_w1[i] = w1g[i];
    if (tid < 16) s_b1[tid] = b1g[tid];
    if (tid < 32) s_b2[tid] = b2g[tid];
    if (tid < 16) s_feat[tid] = dbg[tid & 3];
    __syncthreads();

    // ---------------- conv1 (3x3x1x16) + relu + 2x2 maxpool -> s_p1[4][16][12][12] --
    // half-row units: (im, co, py, half). nimg*384 units over 320 threads.
    for (int u = tid; u < nimg * 384; u += 320) {
        const int im   = u / 384;
        const int rem  = u - im * 384;
        const int half = rem & 1;
        const int idx  = rem >> 1;          // 0..191
        const int co   = idx & 15;
        const int py   = idx >> 4;          // 0..11
        float w[9];
        #pragma unroll
        for (int k = 0; k < 9; k++) w[k] = s_w1[k * 16 + co];
        const float bias = s_b1[co];
        const float* in0 = s_img + im * 784 + (2 * py) * 28;
        float* p1row = s_p1 + im * 2304 + (co * 12 + py) * 12;
        const int px0 = half * 6;

        float win[4][4];
        #pragma unroll
        for (int r = 0; r < 4; r++) {
            const float2 v = *(const float2*)(in0 + r * 28 + 2 * px0);
            win[r][2] = v.x; win[r][3] = v.y;
        }
        #pragma unroll
        for (int dpx = 0; dpx < 6; dpx++) {
            const int px = px0 + dpx;
            #pragma unroll
            for (int r = 0; r < 4; r++) {
                win[r][0] = win[r][2];
                win[r][1] = win[r][3];
                const float2 v = *(const float2*)(in0 + r * 28 + 2 * px + 2);
                win[r][2] = v.x; win[r][3] = v.y;
            }
            float best = -1e30f;
            #pragma unroll
            for (int dy = 0; dy < 2; dy++) {
                #pragma unroll
                for (int dx = 0; dx < 2; dx++) {
                    float acc = bias;
                    #pragma unroll
                    for (int ky = 0; ky < 3; ky++) {
                        #pragma unroll
                        for (int kx = 0; kx < 3; kx++)
                            acc += win[dy + ky][dx + kx] * w[ky * 3 + kx];
                    }
                    best = fmaxf(best, acc);
                }
            }
            p1row[px] = fmaxf(best, 0.0f);
        }
    }
    __syncthreads();

    // ---------------- conv2 (3x3x16x32) + relu + FUSED 2x2 maxpool -> s_p2 ---------
    // thread = (imp, co, oyp): 2 x 32 x 5 = 320 units. imp handles images
    // {2*imp, 2*imp+1} sharing one weight load: 40 accumulators.
    {
        const int imp = tid >= 160;
        const int t   = tid - imp * 160;   // mod-160 (160 is not a pow2 mask!)
        const int co  = t & 31;
        const int oyp = t >> 5;            // 0..4
        const float bias = s_b2[co];
        float acc[2][2][10];               // [img-in-pair][out-row][ox]
        #pragma unroll
        for (int g = 0; g < 2; g++)
            #pragma unroll
            for (int rr = 0; rr < 2; rr++)
                #pragma unroll
                for (int i = 0; i < 10; i++) acc[g][rr][i] = bias;

        const float* p1b0 = s_p1 + (2 * imp)     * 2304;
        const float* p1b1 = s_p1 + (2 * imp + 1) * 2304;

        #pragma unroll 1
        for (int ci = 0; ci < 16; ci++) {
            const float* wbase = s_w2 + ci * 32 + co;  // lanes=co: conflict-free
            float w[9];
            #pragma unroll
            for (int k = 0; k < 9; k++) w[k] = wbase[k * 512];

            const int rbase = (ci * 12 + 2 * oyp) * 12;
            #pragma unroll
            for (int g = 0; g < 2; g++) {
                const float* rb = (g ? p1b1 : p1b0) + rbase;
                #pragma unroll
                for (int r = 0; r < 4; r++) {
                    const float4* rp = (const float4*)(rb + r * 12);
                    const float4 A = rp[0], Bv = rp[1], C = rp[2];
                    const float a[12] = {A.x, A.y, A.z, A.w, Bv.x, Bv.y, Bv.z, Bv.w,
                                         C.x, C.y, C.z, C.w};
                    if (r < 3) {           // row r = tap-row r for output row 0
                        const float w0 = w[r * 3], w1 = w[r * 3 + 1], w2 = w[r * 3 + 2];
                        #pragma unroll
                        for (int ox = 0; ox < 10; ox++) {
                            acc[g][0][ox] += a[ox] * w0;
                            acc[g][0][ox] += a[ox + 1] * w1;
                            acc[g][0][ox] += a[ox + 2] * w2;
                        }
                    }
                    if (r >= 1) {          // row r = tap-row r-1 for output row 1
                        const float w0 = w[(r - 1) * 3], w1 = w[(r - 1) * 3 + 1],
                                    w2 = w[(r - 1) * 3 + 2];
                        #pragma unroll
                        for (int ox = 0; ox < 10; ox++) {
                            acc[g][1][ox] += a[ox] * w0;
                            acc[g][1][ox] += a[ox + 1] * w1;
                            acc[g][1][ox] += a[ox + 2] * w2;
                        }
                    }
                }
            }
        }
        // fused relu + 2x2 pool, NHWC flatten [(oyp*5+c)*32+co]
        #pragma unroll
        for (int g = 0; g < 2; g++) {
            float* dst = s_p2 + (2 * imp + g) * 800 + (oyp * 5) * 32 + co;
            #pragma unroll
            for (int c = 0; c < 5; c++) {
                const float m = fmaxf(fmaxf(acc[g][0][2 * c], acc[g][0][2 * c + 1]),
                                      fmaxf(acc[g][1][2 * c], acc[g][1][2 * c + 1]));
                dst[c * 32] = fmaxf(m, 0.0f);
            }
        }
    }
    __syncthreads();

    // ---------------- dense 800 -> 4, four images (one weight load serves all) -----
    {
        float p[4][4];
        #pragma unroll
        for (int g = 0; g < 4; g++)
            #pragma unroll
            for (int c = 0; c < 4; c++) p[g][c] = 0.0f;

        for (int k = tid; k < 800; k += 320) {
            const float4 w = *(const float4*)(dwg + k * 4);
            #pragma unroll
            for (int g = 0; g < 4; g++) {
                const float v = s_p2[g * 800 + k];
                p[g][0] += v * w.x; p[g][1] += v * w.y;
                p[g][2] += v * w.z; p[g][3] += v * w.w;
            }
        }
        #pragma unroll
        for (int off = 16; off; off >>= 1) {
            #pragma unroll
            for (int g = 0; g < 4; g++) {
                #pragma unroll
                for (int c = 0; c < 4; c++)
                    p[g][c] += __shfl_down_sync(0xffffffffu, p[g][c], off);
            }
        }
        if ((tid & 31) == 0) {
            #pragma unroll
            for (int g = 0; g < 4; g++) {
                #pragma unroll
                for (int c = 0; c < 4; c++)
                    atomicAdd(&s_feat[g * 4 + c], p[g][c]);
            }
        }
    }
    __syncthreads();

    // ---------------- analytic quantum circuit + sigmoid ---------------------------
    if (tid < 16) {
        const int im = tid >> 2;
        const int j  = tid & 3;
        const int img = img0 + im;
        if (img < B) {
            float pr1[4];
            #pragma unroll
            for (int i = 0; i < 4; i++) {
                const float f = tanhf(s_feat[im * 4 + i]);
                pr1[i] = 0.5f * (1.0f + sinf(f));
            }
            float wj[4];
            #pragma unroll
            for (int i = 0; i < 4; i++) wj[i] = qwg[i * 4 + j];

            float q = 0.0f;
            #pragma unroll
            for (int b = 0; b < 16; b++) {
                float prob = 1.0f, ang = 0.0f;
                #pragma unroll
                for (int i = 0; i < 4; i++) {
                    if (b & (1 << i)) { prob *= pr1[i];        ang += wj[i]; }
                    else              { prob *= 1.0f - pr1[i]; }
                }
                q -= prob * sinf(ang);
            }
            out[img * 4 + j] = 1.0f / (1.0f + expf(-10.0f * q));
        }
    }
}

extern "C" void kernel_launch(void* const* d_in, const int* in_sizes, int n_in,
                              void* d_out, int out_size)
{
    const float* x   = (const float*)d_in[0];
    const float* w1  = (const float*)d_in[1];
    const float* b1  = (const float*)d_in[2];
    const float* w2  = (const float*)d_in[3];
    const float* b2  = (const float*)d_in[4];
    const float* dw  = (const float*)d_in[5];
    const float* db  = (const float*)d_in[6];
    const float* qw  = (const float*)d_in[7];
    float* out = (float*)d_out;

    const int B = in_sizes[0] / 784;   // NHWC 28*28*1
    static bool attr_set = false;
    if (!attr_set) {
        cudaFuncSetAttribute(hybrid_kernel,
                             cudaFuncAttributeMaxDynamicSharedMemorySize, SM_BYTES);
        attr_set = true;
    }
    hybrid_kernel<<<(B + 3) / 4, 320, SM_BYTES>>>(x, w1, b1, w2, b2, dw, db, qw, out, B);
}